// round 11
// baseline (speedup 1.0000x reference)
#include <cuda_runtime.h>
#include <math.h>

#define N_NODES 100000
#define N_EDGES 1000000
#define D_NODE 64
#define D_EDGE 16
#define NUM_PAR 80
#define HIDDEN 160

#define NBLOCKS 888               // 148 SMs x 6 blocks, all co-resident
#define NTHREADS 256              // 8 warps
#define EPT 5                     // edges per thread: 888*256*5 = 1,136,640 >= 1e6

// Scratch (allocation-free rule).
__device__ float g_p[N_NODES];
__device__ int   g_cnt;           // barrier arrivals (self-resetting)
__device__ volatile int g_flag;   // barrier generation (monotone across replays)

// Warp-cooperative collapsed weight for one row r of W1:
//   w[r] = sum_j W1[r,j] * W2[j], lane-parallel over j (5 strides of 32).
__device__ __forceinline__ float collapse_row(const float* __restrict__ W1,
                                              const float* __restrict__ w2reg,
                                              int r, int lane) {
    const float* row = W1 + r * HIDDEN;
    float s = 0.f;
    #pragma unroll
    for (int k = 0; k < 5; k++)
        s = fmaf(__ldg(row + lane + 32 * k), w2reg[k], s);
    #pragma unroll
    for (int o = 16; o > 0; o >>= 1)
        s += __shfl_xor_sync(0xFFFFFFFFu, s, o);
    return s;   // valid in all lanes
}

// ---------------------------------------------------------------------------
// Fused persistent kernel (6 blocks/SM -> 48 warps/SM).
//   Stage 0: per-block weight collapse (W1/W2 L2-resident after wave 1).
//   Stage 1: node projections p[n] = x[n].w[0:64]  (warp: 2 nodes/iter,
//            lane loads float4, 16-lane shuffle tree; unrolled x2).
//   Stage 2 (pre-barrier, independent of p): this thread's 5 edges:
//            indices (coalesced low-word loads; int32/int64 via stride mult)
//            and q[k] = ea[e].w[64:80] + c  (streams 68MB, overlaps
//            stragglers' node work across SMs; loads independent across k).
//   Barrier: sense-reversing grid barrier (all blocks resident by design).
//   Stage 3: 10 scattered p-gathers (L2-resident 400KB), out = sigmoid(ps+q).
// ---------------------------------------------------------------------------
__global__ __launch_bounds__(NTHREADS, 6)
void fused_kernel(const float* __restrict__ x,
                  const void*  __restrict__ ei_raw,
                  const float* __restrict__ ea,
                  const float* __restrict__ W1,
                  const float* __restrict__ b1,
                  const float* __restrict__ W2,
                  const float* __restrict__ b2,
                  float* __restrict__ out) {
    __shared__ float sw[NUM_PAR];
    __shared__ float sc;
    __shared__ int   smult;
    int t = threadIdx.x;
    int warp = t >> 5;
    int lane = t & 31;

    // ---- Stage 0: weight collapse (all 8 warps; 10 rows each) ----
    {
        float w2[5];
        #pragma unroll
        for (int k = 0; k < 5; k++) w2[k] = __ldg(W2 + lane + 32 * k);
        #pragma unroll
        for (int rr = 0; rr < 10; rr++) {
            int r = warp * 10 + rr;
            float s = collapse_row(W1, w2, r, lane);
            if (lane == 0) sw[r] = s;
        }
        if (warp == 7) {   // c = b1 . W2 + b2
            float s = 0.f;
            #pragma unroll
            for (int k = 0; k < 5; k++)
                s = fmaf(__ldg(b1 + lane + 32 * k), w2[k], s);
            #pragma unroll
            for (int o = 16; o > 0; o >>= 1)
                s += __shfl_xor_sync(0xFFFFFFFFu, s, o);
            if (lane == 0) sc = s + __ldg(b2);
        }
        if (warp == 0) {
            // Dtype probe: 32 entries as int64 all in [0,N_NODES) <=> int64
            // (int32 data would need 32 zero hi-words: P ~ 1e-160).
            const long long* ei64 = (const long long*)ei_raw;
            long long v = __ldg(ei64 + lane);
            unsigned b = __ballot_sync(0xFFFFFFFFu, v >= 0 && v < N_NODES);
            if (lane == 0) smult = (b == 0xFFFFFFFFu) ? 2 : 1;
        }
    }
    __syncthreads();

    // ---- Stage 1: node projections (2 nodes/warp/iter, unroll x2) ----
    {
        int half = lane >> 4;
        int q    = lane & 15;
        float w0 = sw[q * 4 + 0];
        float w1 = sw[q * 4 + 1];
        float w2r = sw[q * 4 + 2];
        float w3 = sw[q * 4 + 3];

        const float4* x4 = (const float4*)x;
        const int stride = NBLOCKS * 16;   // nodes covered per sweep

        #pragma unroll 2
        for (int node = blockIdx.x * 16 + warp * 2 + half;
             node < N_NODES; node += stride) {
            float4 v = __ldg(x4 + (size_t)node * 16 + q);
            float s = fmaf(v.x, w0, fmaf(v.y, w1, fmaf(v.z, w2r, v.w * w3)));
            #pragma unroll
            for (int o = 8; o > 0; o >>= 1)
                s += __shfl_xor_sync(0xFFFFFFFFu, s, o);
            if (q == 0) g_p[node] = s;
        }
    }

    // ---- Stage 2 (pre-barrier): indices + q = ea.w + c ----
    const int mult = smult;
    const float cc = sc;
    const int* eidx = (const int*)ei_raw;   // low 4B hold the value (LE)
    const int base = blockIdx.x * (NTHREADS * EPT) + t;

    int srcs[EPT], dsts[EPT];
    #pragma unroll
    for (int k = 0; k < EPT; k++) {
        int e  = base + k * NTHREADS;
        int ec = e < N_EDGES ? e : (N_EDGES - 1);
        srcs[k] = __ldg(eidx + (size_t)mult * ec);
        dsts[k] = __ldg(eidx + (size_t)mult * ((size_t)N_EDGES + ec));
    }

    float q[EPT];
    #pragma unroll
    for (int k = 0; k < EPT; k++) {
        int e  = base + k * NTHREADS;
        int ec = e < N_EDGES ? e : (N_EDGES - 1);
        const float4* A = (const float4*)(ea + (size_t)ec * D_EDGE);
        float4 a0 = __ldg(A + 0);
        float4 a1 = __ldg(A + 1);
        float4 a2 = __ldg(A + 2);
        float4 a3 = __ldg(A + 3);
        float z0 = fmaf(a0.x, sw[64], fmaf(a0.y, sw[65], fmaf(a0.z, sw[66], a0.w * sw[67])));
        float z1 = fmaf(a1.x, sw[68], fmaf(a1.y, sw[69], fmaf(a1.z, sw[70], a1.w * sw[71])));
        float z2 = fmaf(a2.x, sw[72], fmaf(a2.y, sw[73], fmaf(a2.z, sw[74], a2.w * sw[75])));
        float z3 = fmaf(a3.x, sw[76], fmaf(a3.y, sw[77], fmaf(a3.z, sw[78], a3.w * sw[79])));
        q[k] = cc + ((z0 + z1) + (z2 + z3));
    }

    // ---- Grid barrier (sense-reversing; all blocks resident) ----
    __syncthreads();
    if (t == 0) {
        int gen = g_flag;                    // same value in all blocks:
        __threadfence();                     // flag only moves after all arrive
        int a = atomicAdd(&g_cnt, 1);
        if (a == NBLOCKS - 1) {
            g_cnt = 0;                       // self-reset for next replay
            __threadfence();
            g_flag = gen + 1;                // release
        } else {
            while (g_flag == gen) { }        // spin (volatile)
        }
        __threadfence();
    }
    __syncthreads();

    // ---- Stage 3: scattered gathers + finish ----
    float ps[EPT];
    #pragma unroll
    for (int k = 0; k < EPT; k++)
        ps[k] = g_p[srcs[k]] + g_p[dsts[k]];

    #pragma unroll
    for (int k = 0; k < EPT; k++) {
        int e = base + k * NTHREADS;
        if (e < N_EDGES) {
            float z = ps[k] + q[k];
            out[e] = 1.0f / (1.0f + __expf(-z));
        }
    }
}

extern "C" void kernel_launch(void* const* d_in, const int* in_sizes, int n_in,
                              void* d_out, int out_size) {
    // metadata order: x, edge_index, edge_attr, W1, b1, W2, b2
    const float* x  = (const float*)d_in[0];
    const void*  ei = d_in[1];
    const float* ea = (const float*)d_in[2];
    const float* W1 = (const float*)d_in[3];
    const float* b1 = (const float*)d_in[4];
    const float* W2 = (const float*)d_in[5];
    const float* b2 = (const float*)d_in[6];
    float* out = (float*)d_out;

    fused_kernel<<<NBLOCKS, NTHREADS>>>(x, ei, ea, W1, b1, W2, b2, out);
}

// round 12
// speedup vs baseline: 1.0724x; 1.0724x over previous
#include <cuda_runtime.h>
#include <math.h>

#define N_NODES 100000
#define N_EDGES 1000000
#define D_NODE 64
#define D_EDGE 16
#define NUM_PAR 80
#define HIDDEN 160

#define NBLOCKS 592               // 148 SMs x 4 blocks, all co-resident
#define NTHREADS 256              // 8 warps
#define EPT 7                     // edges per thread: 592*256*7 = 1,060,864 >= 1e6

// Scratch (allocation-free rule).
__device__ float g_p[N_NODES];
__device__ int   g_cnt;           // barrier arrivals (self-resetting)
__device__ volatile int g_flag;   // barrier generation (monotone across replays)

// Warp-cooperative collapsed weight for one row r of W1:
//   w[r] = sum_j W1[r,j] * W2[j], lane-parallel over j (5 strides of 32).
__device__ __forceinline__ float collapse_row(const float* __restrict__ W1,
                                              const float* __restrict__ w2reg,
                                              int r, int lane) {
    const float* row = W1 + r * HIDDEN;
    float s = 0.f;
    #pragma unroll
    for (int k = 0; k < 5; k++)
        s = fmaf(__ldg(row + lane + 32 * k), w2reg[k], s);
    #pragma unroll
    for (int o = 16; o > 0; o >>= 1)
        s += __shfl_xor_sync(0xFFFFFFFFu, s, o);
    return s;   // valid in all lanes
}

// ---------------------------------------------------------------------------
// Fused persistent kernel (4 blocks/SM).
//   Stage 0: per-block weight collapse (W1/W2 L2-resident after wave 1).
//   Stage 1: node projections p[n] = x[n].w[0:64].
//   Stage 2 (pre-barrier, independent of p): indices + q[k] = ea.w[64:80]+c.
//     Quad-cooperative ea: per 32-edge chunk, 4 rounds of LDG.128 over 32
//     CONSECUTIVE float4s (4 wavefronts/round, fully-used 128B lines, vs 16
//     for the strided per-thread layout). A quad of lanes holds one edge row:
//     partial dot + 2x shfl_xor; then 4 shuffles redistribute q so lane l
//     owns edge chunk+l (matching the gather layout).
//   Barrier: sense-reversing grid barrier (all blocks resident by design).
//   Stage 3: 14 scattered p-gathers (L2-resident 400KB), out = sigmoid(ps+q).
// ---------------------------------------------------------------------------
__global__ __launch_bounds__(NTHREADS, 4)
void fused_kernel(const float* __restrict__ x,
                  const void*  __restrict__ ei_raw,
                  const float* __restrict__ ea,
                  const float* __restrict__ W1,
                  const float* __restrict__ b1,
                  const float* __restrict__ W2,
                  const float* __restrict__ b2,
                  float* __restrict__ out) {
    __shared__ float sw[NUM_PAR];
    __shared__ float sc;
    __shared__ int   smult;
    int t = threadIdx.x;
    int warp = t >> 5;
    int lane = t & 31;

    // ---- Stage 0: weight collapse (all 8 warps; 10 rows each) ----
    {
        float w2[5];
        #pragma unroll
        for (int k = 0; k < 5; k++) w2[k] = __ldg(W2 + lane + 32 * k);
        #pragma unroll
        for (int rr = 0; rr < 10; rr++) {
            int r = warp * 10 + rr;
            float s = collapse_row(W1, w2, r, lane);
            if (lane == 0) sw[r] = s;
        }
        if (warp == 7) {   // c = b1 . W2 + b2
            float s = 0.f;
            #pragma unroll
            for (int k = 0; k < 5; k++)
                s = fmaf(__ldg(b1 + lane + 32 * k), w2[k], s);
            #pragma unroll
            for (int o = 16; o > 0; o >>= 1)
                s += __shfl_xor_sync(0xFFFFFFFFu, s, o);
            if (lane == 0) sc = s + __ldg(b2);
        }
        if (warp == 0) {
            // Dtype probe: 32 entries as int64 all in [0,N_NODES) <=> int64
            // (int32 data would need 32 zero hi-words: P ~ 1e-160).
            const long long* ei64 = (const long long*)ei_raw;
            long long v = __ldg(ei64 + lane);
            unsigned b = __ballot_sync(0xFFFFFFFFu, v >= 0 && v < N_NODES);
            if (lane == 0) smult = (b == 0xFFFFFFFFu) ? 2 : 1;
        }
    }
    __syncthreads();

    // ---- Stage 1: node projections (2 nodes/warp/iter) ----
    {
        int half = lane >> 4;
        int q    = lane & 15;
        float w0 = sw[q * 4 + 0];
        float w1 = sw[q * 4 + 1];
        float w2r = sw[q * 4 + 2];
        float w3 = sw[q * 4 + 3];

        const float4* x4 = (const float4*)x;
        const int stride = NBLOCKS * 16;

        for (int node = blockIdx.x * 16 + warp * 2 + half;
             node < N_NODES; node += stride) {
            float4 v = __ldg(x4 + (size_t)node * 16 + q);
            float s = fmaf(v.x, w0, fmaf(v.y, w1, fmaf(v.z, w2r, v.w * w3)));
            #pragma unroll
            for (int o = 8; o > 0; o >>= 1)
                s += __shfl_xor_sync(0xFFFFFFFFu, s, o);
            if (q == 0) g_p[node] = s;
        }
    }

    // ---- Stage 2 (pre-barrier): indices + quad-cooperative q ----
    const int mult = smult;
    const float cc = sc;
    const int* eidx = (const int*)ei_raw;   // low 4B hold the value (LE)
    const int base = blockIdx.x * (NTHREADS * EPT) + t;

    int srcs[EPT], dsts[EPT];
    #pragma unroll
    for (int k = 0; k < EPT; k++) {
        int e  = base + k * NTHREADS;
        int ec = e < N_EDGES ? e : (N_EDGES - 1);
        srcs[k] = __ldg(eidx + (size_t)mult * ec);
        dsts[k] = __ldg(eidx + (size_t)mult * ((size_t)N_EDGES + ec));
    }

    // Per-lane quad weights: lane handles component group j = lane&3.
    const int j4 = (lane & 3) * 4;
    const float rwa = sw[64 + j4 + 0];
    const float rwb = sw[64 + j4 + 1];
    const float rwc = sw[64 + j4 + 2];
    const float rwd = sw[64 + j4 + 3];
    const float4* ea4 = (const float4*)ea;
    const int N4 = N_EDGES * 4;
    const int redistrib_src = 4 * (lane & 7);

    float q[EPT];
    #pragma unroll
    for (int k = 0; k < EPT; k++) {
        // This warp's 32-edge chunk for step k (lane l <-> edge chunk+l).
        int chunk = blockIdx.x * (NTHREADS * EPT) + k * NTHREADS + warp * 32;
        int f0 = chunk * 4;
        float qr[4];
        #pragma unroll
        for (int r = 0; r < 4; r++) {
            int fi = f0 + r * 32 + lane;          // 32 consecutive float4s
            if (fi >= N4) fi = N4 - 1;            // clamped; result unused
            float4 a = __ldg(ea4 + fi);
            float s = fmaf(a.x, rwa, fmaf(a.y, rwb, fmaf(a.z, rwc, a.w * rwd)));
            s += __shfl_xor_sync(0xFFFFFFFFu, s, 1);
            s += __shfl_xor_sync(0xFFFFFFFFu, s, 2);
            qr[r] = s;                            // full dot of edge r*8 + lane/4
        }
        // Redistribute: lane l wants edge l = 8r+m -> round r, source lane 4m.
        float v0 = __shfl_sync(0xFFFFFFFFu, qr[0], redistrib_src);
        float v1 = __shfl_sync(0xFFFFFFFFu, qr[1], redistrib_src);
        float v2 = __shfl_sync(0xFFFFFFFFu, qr[2], redistrib_src);
        float v3 = __shfl_sync(0xFFFFFFFFu, qr[3], redistrib_src);
        float v  = (lane < 16) ? ((lane < 8) ? v0 : v1)
                               : ((lane < 24) ? v2 : v3);
        q[k] = cc + v;
    }

    // ---- Grid barrier (sense-reversing; all blocks resident) ----
    __syncthreads();
    if (t == 0) {
        int gen = g_flag;
        __threadfence();
        int a = atomicAdd(&g_cnt, 1);
        if (a == NBLOCKS - 1) {
            g_cnt = 0;                       // self-reset for next replay
            __threadfence();
            g_flag = gen + 1;                // release
        } else {
            while (g_flag == gen) { }        // spin (volatile)
        }
        __threadfence();
    }
    __syncthreads();

    // ---- Stage 3: scattered gathers + finish ----
    float ps[EPT];
    #pragma unroll
    for (int k = 0; k < EPT; k++)
        ps[k] = g_p[srcs[k]] + g_p[dsts[k]];

    #pragma unroll
    for (int k = 0; k < EPT; k++) {
        int e = base + k * NTHREADS;
        if (e < N_EDGES) {
            float z = ps[k] + q[k];
            out[e] = 1.0f / (1.0f + __expf(-z));
        }
    }
}

extern "C" void kernel_launch(void* const* d_in, const int* in_sizes, int n_in,
                              void* d_out, int out_size) {
    // metadata order: x, edge_index, edge_attr, W1, b1, W2, b2
    const float* x  = (const float*)d_in[0];
    const void*  ei = d_in[1];
    const float* ea = (const float*)d_in[2];
    const float* W1 = (const float*)d_in[3];
    const float* b1 = (const float*)d_in[4];
    const float* W2 = (const float*)d_in[5];
    const float* b2 = (const float*)d_in[6];
    float* out = (float*)d_out;

    fused_kernel<<<NBLOCKS, NTHREADS>>>(x, ei, ea, W1, b1, W2, b2, out);
}